// round 14
// baseline (speedup 1.0000x reference)
#include <cuda_runtime.h>

typedef unsigned long long u64;
typedef unsigned int u32;

#define T_STEPS 2048
#define NB 8
#define NH 16
#define BH (NB*NH)
#define KF 32
#define VF 64
#define KS 128
#define VS 64

// ---- packed f32x2 helpers ----
__device__ __forceinline__ u64 pack2(float lo, float hi) {
    u64 r;
    asm("mov.b64 %0, {%1, %2};" : "=l"(r) : "r"(__float_as_uint(lo)), "r"(__float_as_uint(hi)));
    return r;
}
__device__ __forceinline__ void unpack2(u64 a, float& lo, float& hi) {
    u32 l, h;
    asm("mov.b64 {%0, %1}, %2;" : "=r"(l), "=r"(h) : "l"(a));
    lo = __uint_as_float(l); hi = __uint_as_float(h);
}
__device__ __forceinline__ u64 fma2_(u64 a, u64 b, u64 c) {
    u64 d; asm("fma.rn.f32x2 %0, %1, %2, %3;" : "=l"(d) : "l"(a), "l"(b), "l"(c)); return d;
}
__device__ __forceinline__ u64 mul2_(u64 a, u64 b) {
    u64 d; asm("mul.rn.f32x2 %0, %1, %2;" : "=l"(d) : "l"(a), "l"(b)); return d;
}
__device__ __forceinline__ u64 add2_(u64 a, u64 b) {
    u64 d; asm("add.rn.f32x2 %0, %1, %2;" : "=l"(d) : "l"(a), "l"(b)); return d;
}
__device__ __forceinline__ u64 shfl_xor_u64(u64 v, int m) {
    u32 lo, hi;
    asm("mov.b64 {%0, %1}, %2;" : "=r"(lo), "=r"(hi) : "l"(v));
    lo = __shfl_xor_sync(0xffffffffu, lo, m);
    hi = __shfl_xor_sync(0xffffffffu, hi, m);
    u64 r;
    asm("mov.b64 %0, {%1, %2};" : "=l"(r) : "r"(lo), "r"(hi));
    return r;
}

// ---- mbarrier helpers ----
__device__ __forceinline__ void mbar_init(u32 addr, u32 count) {
    asm volatile("mbarrier.init.shared.b64 [%0], %1;" :: "r"(addr), "r"(count) : "memory");
}
__device__ __forceinline__ void mbar_arrive(u32 addr) {
    asm volatile("mbarrier.arrive.release.cta.shared::cta.b64 _, [%0];" :: "r"(addr) : "memory");
}
__device__ __forceinline__ void mbar_wait(u32 addr, u32 parity) {
    asm volatile(
        "{\n\t.reg .pred P;\n\t"
        "WL%=:\n\t"
        "mbarrier.try_wait.parity.acquire.cta.shared::cta.b64 P, [%0], %1, 0x989680;\n\t"
        "@P bra WD%=;\n\t"
        "bra WL%=;\n\t"
        "WD%=:\n\t}"
        :: "r"(addr), "r"(parity) : "memory");
}
__device__ __forceinline__ void cp16(u32 dst, const void* s) {
    asm volatile("cp.async.cg.shared.global [%0], [%1], 16;" :: "r"(dst), "l"(s));
}
__device__ __forceinline__ void cp4(u32 dst, const void* s) {
    asm volatile("cp.async.ca.shared.global [%0], [%1], 4;" :: "r"(dst), "l"(s));
}
// global fp32 reduction add (no return — off the critical path)
__device__ __forceinline__ void red_add(float* p, float v) {
    asm volatile("red.global.add.f32 [%0], %1;" :: "l"(p), "f"(v) : "memory");
}

// smem per-step stage (floats) — natural order:
// [0,32) kf | [32,64) qf | [64,192) ks | [192,320) qs
// [320,384) vf | [384,448) vs | [448,453) scalars {df,ds,g,mf,ms} | pad 456
#define STEP_F 456
#define MEGA   8
#define NMEGA  3                 // ring = 24 steps = 43.8 KB
#define NMEGAI (T_STEPS/MEGA)

#define NCWARP 16                // 2 K-halves x 8 column-groups
#define NTHREADS (NCWARP*32 + 32)

// per-step register staging (double-buffered)
struct SR {
    float4 sc4;            // df, ds, g, mf
    float  msv;            // ms
    float  kf, qf;         // fast k/q (kg==0 only), row = lane
    float2 ks2, qs2;       // slow k/q, rows 64kg+2l, +1
    ulonglong2 vfA, vfB;   // v_fast cols 8cg..8cg+7 (kg==0 only)
    ulonglong2 vsA, vsB;   // v_slow cols 8cg..8cg+7
};

__device__ __forceinline__ void loadregs(SR& r, const float* cur, int l, int kg, int cg) {
    r.sc4 = *(const float4*)(cur + 448);
    r.msv = cur[452];
    r.ks2 = *(const float2*)(cur + 64  + 64*kg + 2*l);
    r.qs2 = *(const float2*)(cur + 192 + 64*kg + 2*l);
    r.vsA = *(const ulonglong2*)(cur + 384 + 8*cg);
    r.vsB = *(const ulonglong2*)(cur + 384 + 8*cg + 4);
    if (kg == 0) {
        r.kf  = cur[l];
        r.qf  = cur[32 + l];
        r.vfA = *(const ulonglong2*)(cur + 320 + 8*cg);
        r.vfB = *(const ulonglong2*)(cur + 320 + 8*cg + 4);
    }
}

__global__ __launch_bounds__(NTHREADS, 1)
void e90_kernel(const float* __restrict__ k_fast, const float* __restrict__ v_fast,
                const float* __restrict__ q_fast, const float* __restrict__ decay_fast,
                const float* __restrict__ k_slow, const float* __restrict__ v_slow,
                const float* __restrict__ q_slow, const float* __restrict__ decay_slow,
                const float* __restrict__ slow_gate, const float* __restrict__ mix_fast,
                const float* __restrict__ mix_slow, const float* __restrict__ S_fast0,
                const float* __restrict__ S_slow0, float* __restrict__ out)
{
    __shared__ __align__(16) float ring[NMEGA * MEGA * STEP_F];
    __shared__ __align__(8)  u64  mbar[2 * NMEGA];   // [0..2] full, [3..5] empty

    const int tid = threadIdx.x;
    const int bh  = blockIdx.x;

    const u32 sb = (u32)__cvta_generic_to_shared(ring);
    const u32 bb = (u32)__cvta_generic_to_shared(mbar);

    if (tid == 0) {
        #pragma unroll
        for (int i = 0; i < NMEGA; i++) {
            mbar_init(bb + i*8, 32);                 // full: 32 producer-lane arrives
            mbar_init(bb + (NMEGA + i)*8, NCWARP);   // empty: 16 consumer-warp arrives
        }
    }
    __syncthreads();   // the ONLY block barrier

    if (tid >= NCWARP*32) {
        // ================= PRODUCER WARP =================
        const int lane = tid - NCWARP*32;
        const float* src[4];
        int off[4], strd[4], wid[4];
        #pragma unroll
        for (int r = 0; r < 4; r++) {
            int c = r*32 + lane;
            src[r] = 0; off[r] = -1; strd[r] = 0; wid[r] = 1;
            if (c < 8)        {               src[r] = k_fast + (size_t)bh*KF + c*4;  off[r] = c*4;           strd[r] = BH*KF; }
            else if (c < 16)  { int g = c-8;  src[r] = q_fast + (size_t)bh*KF + g*4;  off[r] = 32  + g*4;     strd[r] = BH*KF; }
            else if (c < 48)  { int g = c-16; src[r] = k_slow + (size_t)bh*KS + g*4;  off[r] = 64  + g*4;     strd[r] = BH*KS; }
            else if (c < 80)  { int g = c-48; src[r] = q_slow + (size_t)bh*KS + g*4;  off[r] = 192 + g*4;     strd[r] = BH*KS; }
            else if (c < 96)  { int g = c-80; src[r] = v_fast + (size_t)bh*VF + g*4;  off[r] = 320 + g*4;     strd[r] = BH*VF; }
            else if (c < 112) { int g = c-96; src[r] = v_slow + (size_t)bh*VS + g*4;  off[r] = 384 + g*4;     strd[r] = BH*VS; }
            else if (c < 117) {
                const float* a5[5] = {decay_fast, decay_slow, slow_gate, mix_fast, mix_slow};
                src[r] = a5[c-112] + bh; off[r] = 448 + (c-112); strd[r] = BH; wid[r] = 0;
            }
        }

        int sm = 0; u32 eph = 1;
        for (int m = 0; m < NMEGAI; m++) {
            mbar_wait(bb + (NMEGA + sm)*8, eph);     // wait stage free
            u32 stg = sb + (u32)(sm * MEGA * STEP_F) * 4u;
            #pragma unroll
            for (int s = 0; s < MEGA; s++) {
                u32 stp = stg + (u32)(s * STEP_F) * 4u;
                #pragma unroll
                for (int r = 0; r < 4; r++) {
                    if (off[r] >= 0) {
                        u32 dst = stp + (u32)off[r] * 4u;
                        if (wid[r]) cp16(dst, src[r]); else cp4(dst, src[r]);
                        src[r] += strd[r];
                    }
                }
            }
            asm volatile("cp.async.mbarrier.arrive.noinc.shared.b64 [%0];" :: "r"(bb + sm*8) : "memory");
            if (sm == NMEGA-1) { sm = 0; eph ^= 1; } else sm++;
        }
    } else {
        // ================= 16 CONSUMER WARPS =================
        // warp (kg, cg): kg = K-half, cg = column-group (8 output cols).
        // lane l: slow rows 64kg+2l, 64kg+2l+1 ; fast row l (kg==0 only).
        const int w  = tid >> 5;
        const int l  = tid & 31;
        const int kg = w >> 3;
        const int cg = w & 7;

        // states packed along COLUMNS
        u64 Sf[4], Ss[2][4];
        {
            if (kg == 0) {
                const float* p0 = S_fast0 + (size_t)bh*KF*VF + (size_t)l*VF + 8*cg;
                float4 a = *(const float4*)p0;
                float4 b = *(const float4*)(p0 + 4);
                Sf[0] = pack2(a.x, a.y); Sf[1] = pack2(a.z, a.w);
                Sf[2] = pack2(b.x, b.y); Sf[3] = pack2(b.z, b.w);
            }
            #pragma unroll
            for (int p = 0; p < 2; p++) {
                const float* p1 = S_slow0 + (size_t)bh*KS*VS + (size_t)(64*kg + 2*l + p)*VS + 8*cg;
                float4 c = *(const float4*)p1;
                float4 d = *(const float4*)(p1 + 4);
                Ss[p][0] = pack2(c.x, c.y); Ss[p][1] = pack2(c.z, c.w);
                Ss[p][2] = pack2(d.x, d.y); Ss[p][3] = pack2(d.z, d.w);
            }
        }

        float* outO = out + (size_t)BH*(KF*VF + KS*VS) + (size_t)bh*VF + 8*cg;
        const bool elect   = (l == 0);
        const bool writer  = ((l & 3) == 0);     // lanes 0,4,..,28: one column each
        const int  wcol    = l >> 2;
        const bool hi16    = (l & 16) != 0;
        const bool hi8     = (l & 8)  != 0;
        const bool hi4     = (l & 4)  != 0;

        auto compute = [&](const SR& r) {
            float df = r.sc4.x, ds = r.sc4.y, g = r.sc4.z, mf = r.sc4.w;
            float ms = r.msv;
            float de = 1.0f + g * (ds - 1.0f);      // g*ds + (1-g)

            u64 de2 = pack2(de, de);
            u64 g2  = pack2(g, g);
            u64 vs2[4] = { mul2_(g2, r.vsA.x), mul2_(g2, r.vsA.y),
                           mul2_(g2, r.vsB.x), mul2_(g2, r.vsB.y) };

            // slow state: 2 rows x 4 col-pairs
            u64 k0 = pack2(r.ks2.x, r.ks2.x), k1 = pack2(r.ks2.y, r.ks2.y);
            u64 q0 = pack2(r.qs2.x, r.qs2.x), q1 = pack2(r.qs2.y, r.qs2.y);
            u64 accs[4];
            #pragma unroll
            for (int j = 0; j < 4; j++) {
                Ss[0][j] = fma2_(de2, Ss[0][j], mul2_(k0, vs2[j]));
                accs[j]  = mul2_(q0, Ss[0][j]);
            }
            #pragma unroll
            for (int j = 0; j < 4; j++) {
                Ss[1][j] = fma2_(de2, Ss[1][j], mul2_(k1, vs2[j]));
                accs[j]  = fma2_(q1, Ss[1][j], accs[j]);
            }

            // mix
            u64 ms2 = pack2(ms, ms);
            u64 a0, a1, a2, a3;
            if (kg == 0) {
                // fast state: row l x 4 col-pairs
                u64 df2 = pack2(df, df);
                u64 vf2[4] = { r.vfA.x, r.vfA.y, r.vfB.x, r.vfB.y };
                u64 kf2 = pack2(r.kf, r.kf);
                u64 qf2 = pack2(r.qf, r.qf);
                u64 accf[4];
                #pragma unroll
                for (int j = 0; j < 4; j++) {
                    Sf[j]   = fma2_(df2, Sf[j], mul2_(kf2, vf2[j]));
                    accf[j] = mul2_(qf2, Sf[j]);
                }
                u64 mf2 = pack2(mf, mf);
                a0 = fma2_(ms2, accs[0], mul2_(mf2, accf[0]));
                a1 = fma2_(ms2, accs[1], mul2_(mf2, accf[1]));
                a2 = fma2_(ms2, accs[2], mul2_(mf2, accf[2]));
                a3 = fma2_(ms2, accs[3], mul2_(mf2, accf[3]));
            } else {
                a0 = mul2_(ms2, accs[0]);
                a1 = mul2_(ms2, accs[1]);
                a2 = mul2_(ms2, accs[2]);
                a3 = mul2_(ms2, accs[3]);
            }

            // ---- value-halving butterfly over 32 lanes (proven in R12) ----
            u64 sA = hi16 ? a0 : a2;
            u64 sB = hi16 ? a1 : a3;
            u64 kA = hi16 ? a2 : a0;
            u64 kB = hi16 ? a3 : a1;
            kA = add2_(kA, shfl_xor_u64(sA, 16));
            kB = add2_(kB, shfl_xor_u64(sB, 16));
            u64 sC = hi8 ? kA : kB;
            u64 kC = hi8 ? kB : kA;
            kC = add2_(kC, shfl_xor_u64(sC, 8));
            float x, y;
            unpack2(kC, x, y);
            float sD = hi4 ? x : y;
            float kD = hi4 ? y : x;
            kD += __shfl_xor_sync(0xffffffffu, sD, 4);
            kD += __shfl_xor_sync(0xffffffffu, kD, 2);
            kD += __shfl_xor_sync(0xffffffffu, kD, 1);
            // combine the two K-halves: exactly 2 commutative fp32 adds -> deterministic
            if (writer) red_add(outO + wcol, kD);
            outO += (size_t)BH * VF;
        };

        SR R[2];
        int sm = 0; u32 cph = 0;
        mbar_wait(bb + 0, 0);
        loadregs(R[0], ring, l, kg, cg);

        for (int m = 0; m < NMEGAI; m++) {
            const float* base = ring + sm * MEGA * STEP_F;
            const int nsm = (sm == NMEGA-1) ? 0 : sm+1;
            const u32 nc  = (sm == NMEGA-1) ? (cph ^ 1) : cph;
            #pragma unroll
            for (int s = 0; s < MEGA; s++) {
                if (s < MEGA-1) {
                    loadregs(R[(s+1)&1], base + (s+1)*STEP_F, l, kg, cg);
                } else if (m < NMEGAI-1) {
                    mbar_wait(bb + nsm*8, nc);   // hidden under final compute
                    loadregs(R[0], ring + nsm * MEGA * STEP_F, l, kg, cg);
                }
                compute(R[s&1]);
            }
            if (elect) mbar_arrive(bb + (NMEGA + sm)*8);
            sm = nsm; cph = nc;
        }

        // final states
        {
            if (kg == 0) {
                float* oSf = out + (size_t)bh*KF*VF + (size_t)l*VF + 8*cg;
                float a0,a1,a2,a3,b0,b1,b2,b3;
                unpack2(Sf[0], a0, a1); unpack2(Sf[1], a2, a3);
                unpack2(Sf[2], b0, b1); unpack2(Sf[3], b2, b3);
                *(float4*)oSf       = make_float4(a0, a1, a2, a3);
                *(float4*)(oSf + 4) = make_float4(b0, b1, b2, b3);
            }
            #pragma unroll
            for (int p = 0; p < 2; p++) {
                float* oSs = out + (size_t)BH*KF*VF + (size_t)bh*KS*VS + (size_t)(64*kg + 2*l + p)*VS + 8*cg;
                float c0,c1,c2,c3,d0,d1,d2,d3;
                unpack2(Ss[p][0], c0, c1); unpack2(Ss[p][1], c2, c3);
                unpack2(Ss[p][2], d0, d1); unpack2(Ss[p][3], d2, d3);
                *(float4*)oSs       = make_float4(c0, c1, c2, c3);
                *(float4*)(oSs + 4) = make_float4(d0, d1, d2, d3);
            }
        }
    }
}

extern "C" void kernel_launch(void* const* d_in, const int* in_sizes, int n_in,
                              void* d_out, int out_size) {
    (void)in_sizes; (void)n_in; (void)out_size;
    // zero the output region (state regions are fully overwritten by plain stores).
    // In-graph memset keeps graph replays idempotent (outputs are RED-accumulated).
    float* outp = (float*)d_out;
    cudaMemsetAsync(outp + (size_t)BH*(KF*VF + KS*VS), 0,
                    (size_t)T_STEPS * BH * VF * sizeof(float));
    e90_kernel<<<BH, NTHREADS>>>(
        (const float*)d_in[0],  (const float*)d_in[1],  (const float*)d_in[2],
        (const float*)d_in[3],  (const float*)d_in[4],  (const float*)d_in[5],
        (const float*)d_in[6],  (const float*)d_in[7],  (const float*)d_in[8],
        (const float*)d_in[9],  (const float*)d_in[10], (const float*)d_in[11],
        (const float*)d_in[12], (float*)d_out);
}

// round 15
// speedup vs baseline: 1.5778x; 1.5778x over previous
#include <cuda_runtime.h>

typedef unsigned long long u64;
typedef unsigned int u32;

#define T_STEPS 2048
#define NB 8
#define NH 16
#define BH (NB*NH)
#define KF 32
#define VF 64
#define KS 128
#define VS 64

// ---- packed f32x2 helpers ----
__device__ __forceinline__ u64 pack2(float lo, float hi) {
    u64 r;
    asm("mov.b64 %0, {%1, %2};" : "=l"(r) : "r"(__float_as_uint(lo)), "r"(__float_as_uint(hi)));
    return r;
}
__device__ __forceinline__ void unpack2(u64 a, float& lo, float& hi) {
    u32 l, h;
    asm("mov.b64 {%0, %1}, %2;" : "=r"(l), "=r"(h) : "l"(a));
    lo = __uint_as_float(l); hi = __uint_as_float(h);
}
__device__ __forceinline__ u64 fma2_(u64 a, u64 b, u64 c) {
    u64 d; asm("fma.rn.f32x2 %0, %1, %2, %3;" : "=l"(d) : "l"(a), "l"(b), "l"(c)); return d;
}
__device__ __forceinline__ u64 mul2_(u64 a, u64 b) {
    u64 d; asm("mul.rn.f32x2 %0, %1, %2;" : "=l"(d) : "l"(a), "l"(b)); return d;
}
__device__ __forceinline__ u64 add2_(u64 a, u64 b) {
    u64 d; asm("add.rn.f32x2 %0, %1, %2;" : "=l"(d) : "l"(a), "l"(b)); return d;
}
__device__ __forceinline__ u64 shfl_xor_u64(u64 v, int m) {
    u32 lo, hi;
    asm("mov.b64 {%0, %1}, %2;" : "=r"(lo), "=r"(hi) : "l"(v));
    lo = __shfl_xor_sync(0xffffffffu, lo, m);
    hi = __shfl_xor_sync(0xffffffffu, hi, m);
    u64 r;
    asm("mov.b64 %0, {%1, %2};" : "=l"(r) : "r"(lo), "r"(hi));
    return r;
}

// ---- mbarrier helpers ----
__device__ __forceinline__ void mbar_init(u32 addr, u32 count) {
    asm volatile("mbarrier.init.shared.b64 [%0], %1;" :: "r"(addr), "r"(count) : "memory");
}
__device__ __forceinline__ void mbar_arrive(u32 addr) {
    asm volatile("mbarrier.arrive.release.cta.shared::cta.b64 _, [%0];" :: "r"(addr) : "memory");
}
__device__ __forceinline__ void mbar_wait(u32 addr, u32 parity) {
    asm volatile(
        "{\n\t.reg .pred P;\n\t"
        "WL%=:\n\t"
        "mbarrier.try_wait.parity.acquire.cta.shared::cta.b64 P, [%0], %1, 0x989680;\n\t"
        "@P bra WD%=;\n\t"
        "bra WL%=;\n\t"
        "WD%=:\n\t}"
        :: "r"(addr), "r"(parity) : "memory");
}
__device__ __forceinline__ void cp16(u32 dst, const void* s) {
    asm volatile("cp.async.cg.shared.global [%0], [%1], 16;" :: "r"(dst), "l"(s));
}
__device__ __forceinline__ void cp4(u32 dst, const void* s) {
    asm volatile("cp.async.ca.shared.global [%0], [%1], 4;" :: "r"(dst), "l"(s));
}

// smem per-step stage (floats) — natural order, no swizzle:
// [0,32) kf | [32,64) qf | [64,192) ks | [192,320) qs
// [320,384) vf | [384,448) vs | [448,453) scalars {df,ds,g,mf,ms} | pad 456
#define STEP_F 456
#define MEGA   8                 // steps per mega-stage (even: butterfly pairs stay inside)
#define NMEGA  3                 // ring = 24 steps = 43.8 KB static smem
#define NMEGAI (T_STEPS/MEGA)    // 256 mega-iterations

// per-step register staging (double-buffered software pipeline)
struct SR {
    float4 sc4;            // df, ds, g, mf
    float  msv;            // ms
    float  kf, qf;         // fast k/q, row = lane
    float4 ks4, qs4;       // slow k/q, rows 4l..4l+3
    ulonglong2 vfA, vfB;   // v_fast cols 8w..8w+7 packed in pairs
    ulonglong2 vsA, vsB;   // v_slow cols 8w..8w+7
};

__device__ __forceinline__ void loadregs(SR& r, const float* cur, int l, int w) {
    r.sc4 = *(const float4*)(cur + 448);
    r.msv = cur[452];
    r.kf  = cur[l];
    r.qf  = cur[32 + l];
    r.ks4 = *(const float4*)(cur + 64  + 4*l);
    r.qs4 = *(const float4*)(cur + 192 + 4*l);
    r.vfA = *(const ulonglong2*)(cur + 320 + 8*w);
    r.vfB = *(const ulonglong2*)(cur + 320 + 8*w + 4);
    r.vsA = *(const ulonglong2*)(cur + 384 + 8*w);
    r.vsB = *(const ulonglong2*)(cur + 384 + 8*w + 4);
}

__global__ __launch_bounds__(288, 1)
void e90_kernel(const float* __restrict__ k_fast, const float* __restrict__ v_fast,
                const float* __restrict__ q_fast, const float* __restrict__ decay_fast,
                const float* __restrict__ k_slow, const float* __restrict__ v_slow,
                const float* __restrict__ q_slow, const float* __restrict__ decay_slow,
                const float* __restrict__ slow_gate, const float* __restrict__ mix_fast,
                const float* __restrict__ mix_slow, const float* __restrict__ S_fast0,
                const float* __restrict__ S_slow0, float* __restrict__ out)
{
    __shared__ __align__(16) float ring[NMEGA * MEGA * STEP_F];
    __shared__ __align__(8)  u64  mbar[2 * NMEGA];   // [0..2] full, [3..5] empty

    const int tid = threadIdx.x;
    const int bh  = blockIdx.x;

    const u32 sb = (u32)__cvta_generic_to_shared(ring);
    const u32 bb = (u32)__cvta_generic_to_shared(mbar);

    if (tid == 0) {
        #pragma unroll
        for (int i = 0; i < NMEGA; i++) {
            mbar_init(bb + i*8, 32);                 // full: 32 producer-lane arrives
            mbar_init(bb + (NMEGA + i)*8, 8);        // empty: 8 consumer-warp arrives
        }
    }
    __syncthreads();   // the ONLY block barrier

    if (tid >= 256) {
        // ================= PRODUCER WARP =================
        const int lane = tid - 256;
        const float* src[4];
        int off[4], strd[4], wid[4];
        #pragma unroll
        for (int r = 0; r < 4; r++) {
            int c = r*32 + lane;
            src[r] = 0; off[r] = -1; strd[r] = 0; wid[r] = 1;
            if (c < 8)        {               src[r] = k_fast + (size_t)bh*KF + c*4;  off[r] = c*4;           strd[r] = BH*KF; }
            else if (c < 16)  { int g = c-8;  src[r] = q_fast + (size_t)bh*KF + g*4;  off[r] = 32  + g*4;     strd[r] = BH*KF; }
            else if (c < 48)  { int g = c-16; src[r] = k_slow + (size_t)bh*KS + g*4;  off[r] = 64  + g*4;     strd[r] = BH*KS; }
            else if (c < 80)  { int g = c-48; src[r] = q_slow + (size_t)bh*KS + g*4;  off[r] = 192 + g*4;     strd[r] = BH*KS; }
            else if (c < 96)  { int g = c-80; src[r] = v_fast + (size_t)bh*VF + g*4;  off[r] = 320 + g*4;     strd[r] = BH*VF; }
            else if (c < 112) { int g = c-96; src[r] = v_slow + (size_t)bh*VS + g*4;  off[r] = 384 + g*4;     strd[r] = BH*VS; }
            else if (c < 117) {
                const float* a5[5] = {decay_fast, decay_slow, slow_gate, mix_fast, mix_slow};
                src[r] = a5[c-112] + bh; off[r] = 448 + (c-112); strd[r] = BH; wid[r] = 0;
            }
        }

        int sm = 0; u32 eph = 1;   // fresh empty barriers pass parity-1 wait immediately
        for (int m = 0; m < NMEGAI; m++) {
            mbar_wait(bb + (NMEGA + sm)*8, eph);     // wait stage free
            u32 stg = sb + (u32)(sm * MEGA * STEP_F) * 4u;
            #pragma unroll
            for (int s = 0; s < MEGA; s++) {
                u32 stp = stg + (u32)(s * STEP_F) * 4u;
                #pragma unroll
                for (int r = 0; r < 4; r++) {
                    if (off[r] >= 0) {
                        u32 dst = stp + (u32)off[r] * 4u;
                        if (wid[r]) cp16(dst, src[r]); else cp4(dst, src[r]);
                        src[r] += strd[r];
                    }
                }
            }
            asm volatile("cp.async.mbarrier.arrive.noinc.shared.b64 [%0];" :: "r"(bb + sm*8) : "memory");
            if (sm == NMEGA-1) { sm = 0; eph ^= 1; } else sm++;
        }
    } else {
        // ================= 8 CONSUMER WARPS =================
        // warp w owns output columns 8w..8w+7; lane l owns fast row l + slow rows 4l..4l+3
        const int w = tid >> 5;
        const int l = tid & 31;

        // states packed along COLUMNS: Sf[j] = (col 8w+2j, 8w+2j+1) of fast row l
        u64 Sf[4], Ss[4][4];
        {
            const float* p0 = S_fast0 + (size_t)bh*KF*VF + (size_t)l*VF + 8*w;
            float4 a = *(const float4*)p0;
            float4 b = *(const float4*)(p0 + 4);
            Sf[0] = pack2(a.x, a.y); Sf[1] = pack2(a.z, a.w);
            Sf[2] = pack2(b.x, b.y); Sf[3] = pack2(b.z, b.w);
            #pragma unroll
            for (int p = 0; p < 4; p++) {
                const float* p1 = S_slow0 + (size_t)bh*KS*VS + (size_t)(4*l + p)*VS + 8*w;
                float4 c = *(const float4*)p1;
                float4 d = *(const float4*)(p1 + 4);
                Ss[p][0] = pack2(c.x, c.y); Ss[p][1] = pack2(c.z, c.w);
                Ss[p][2] = pack2(d.x, d.y); Ss[p][3] = pack2(d.z, d.w);
            }
        }

        float* outO = out + (size_t)BH*(KF*VF + KS*VS) + (size_t)bh*VF + 8*w;
        const bool elect   = (l == 0);
        const bool writer  = ((l & 3) == 0);     // lanes 0,4,..,28 each write one column
        const int  wcol    = l >> 2;             // column (within the warp's 8) this lane writes
        const bool hi16    = (l & 16) != 0;
        const bool hi8     = (l & 8)  != 0;
        const bool hi4     = (l & 4)  != 0;

        // state math for one step; emits the step's mixed col-pair partials a0..a3
        auto compute_state = [&](const SR& r, u64& a0, u64& a1, u64& a2, u64& a3) {
            float df = r.sc4.x, ds = r.sc4.y, g = r.sc4.z, mf = r.sc4.w;
            float ms = r.msv;
            float de = 1.0f + g * (ds - 1.0f);      // g*ds + (1-g)

            u64 df2 = pack2(df, df);
            u64 de2 = pack2(de, de);
            u64 g2  = pack2(g, g);

            u64 vf2[4] = { r.vfA.x, r.vfA.y, r.vfB.x, r.vfB.y };
            u64 vs2[4] = { mul2_(g2, r.vsA.x), mul2_(g2, r.vsA.y),
                           mul2_(g2, r.vsB.x), mul2_(g2, r.vsB.y) };

            u64 kf2 = pack2(r.kf, r.kf);
            u64 qf2 = pack2(r.qf, r.qf);
            u64 accf[4];
            #pragma unroll
            for (int j = 0; j < 4; j++) {
                Sf[j]   = fma2_(df2, Sf[j], mul2_(kf2, vf2[j]));
                accf[j] = mul2_(qf2, Sf[j]);
            }

            const float ksv[4] = { r.ks4.x, r.ks4.y, r.ks4.z, r.ks4.w };
            const float qsv[4] = { r.qs4.x, r.qs4.y, r.qs4.z, r.qs4.w };
            u64 accs[4];
            {
                u64 k2 = pack2(ksv[0], ksv[0]);
                u64 q2 = pack2(qsv[0], qsv[0]);
                #pragma unroll
                for (int j = 0; j < 4; j++) {
                    Ss[0][j] = fma2_(de2, Ss[0][j], mul2_(k2, vs2[j]));
                    accs[j]  = mul2_(q2, Ss[0][j]);
                }
            }
            #pragma unroll
            for (int p = 1; p < 4; p++) {
                u64 k2 = pack2(ksv[p], ksv[p]);
                u64 q2 = pack2(qsv[p], qsv[p]);
                #pragma unroll
                for (int j = 0; j < 4; j++) {
                    Ss[p][j] = fma2_(de2, Ss[p][j], mul2_(k2, vs2[j]));
                    accs[j]  = fma2_(q2, Ss[p][j], accs[j]);
                }
            }

            u64 mf2 = pack2(mf, mf), ms2 = pack2(ms, ms);
            a0 = fma2_(ms2, accs[0], mul2_(mf2, accf[0]));  // cols 8w+0,1
            a1 = fma2_(ms2, accs[1], mul2_(mf2, accf[1]));  // cols 8w+2,3
            a2 = fma2_(ms2, accs[2], mul2_(mf2, accf[2]));  // cols 8w+4,5
            a3 = fma2_(ms2, accs[3], mul2_(mf2, accf[3]));  // cols 8w+6,7
        };

        // stash for the even step of each pair
        u64 X0 = 0, X1 = 0, X2 = 0, X3 = 0;
        float* dstX = 0;

        SR R[2];
        int sm = 0; u32 cph = 0;
        mbar_wait(bb + 0, 0);
        loadregs(R[0], ring, l, w);

        for (int m = 0; m < NMEGAI; m++) {
            const float* base = ring + sm * MEGA * STEP_F;
            const int nsm = (sm == NMEGA-1) ? 0 : sm+1;
            const u32 nc  = (sm == NMEGA-1) ? (cph ^ 1) : cph;
            #pragma unroll
            for (int s = 0; s < MEGA; s++) {
                if (s < MEGA-1) {
                    loadregs(R[(s+1)&1], base + (s+1)*STEP_F, l, w);
                } else if (m < NMEGAI-1) {
                    // cross-boundary preload hidden under this final compute
                    mbar_wait(bb + nsm*8, nc);
                    loadregs(R[0], ring + nsm * MEGA * STEP_F, l, w);
                }

                u64 a0, a1, a2, a3;
                compute_state(R[s&1], a0, a1, a2, a3);

                if ((s & 1) == 0) {
                    // even step: stash partials, defer reduction
                    X0 = a0; X1 = a1; X2 = a2; X3 = a3;
                    dstX = outO;
                } else {
                    // odd step: ONE batched value-halving butterfly for both steps
                    // stage xor16 (keep cols 0-3 low / 4-7 high, both steps)
                    u64 kx0 = hi16 ? X2 : X0, sx0 = hi16 ? X0 : X2;
                    u64 kx1 = hi16 ? X3 : X1, sx1 = hi16 ? X1 : X3;
                    u64 ky0 = hi16 ? a2 : a0, sy0 = hi16 ? a0 : a2;
                    u64 ky1 = hi16 ? a3 : a1, sy1 = hi16 ? a1 : a3;
                    kx0 = add2_(kx0, shfl_xor_u64(sx0, 16));
                    kx1 = add2_(kx1, shfl_xor_u64(sx1, 16));
                    ky0 = add2_(ky0, shfl_xor_u64(sy0, 16));
                    ky1 = add2_(ky1, shfl_xor_u64(sy1, 16));
                    // stage xor8 (keep one col-pair per step)
                    u64 kx = hi8 ? kx1 : kx0, sx = hi8 ? kx0 : kx1;
                    u64 ky = hi8 ? ky1 : ky0, sy = hi8 ? ky0 : ky1;
                    kx = add2_(kx, shfl_xor_u64(sx, 8));
                    ky = add2_(ky, shfl_xor_u64(sy, 8));
                    // stage xor4: repack to (stepX col c, stepY col c)
                    float xa, xb, ya, yb;
                    unpack2(kx, xa, xb);
                    unpack2(ky, ya, yb);
                    u64 Zk = hi4 ? pack2(xb, yb) : pack2(xa, ya);
                    u64 Zs = hi4 ? pack2(xa, ya) : pack2(xb, yb);
                    u64 Z  = add2_(Zk, shfl_xor_u64(Zs, 4));
                    // stages xor2, xor1 (both steps ride in one u64)
                    Z = add2_(Z, shfl_xor_u64(Z, 2));
                    Z = add2_(Z, shfl_xor_u64(Z, 1));
                    if (writer) {
                        float xv, yv;
                        unpack2(Z, xv, yv);
                        dstX[wcol] = xv;   // even step's output
                        outO[wcol] = yv;   // odd step's output
                    }
                }
                outO += (size_t)BH * VF;
            }
            if (elect) mbar_arrive(bb + (NMEGA + sm)*8);   // stage consumed (all reads done)
            sm = nsm; cph = nc;
        }

        // final states
        {
            float* oSf = out + (size_t)bh*KF*VF + (size_t)l*VF + 8*w;
            float a0,a1,a2,a3,b0,b1,b2,b3;
            unpack2(Sf[0], a0, a1); unpack2(Sf[1], a2, a3);
            unpack2(Sf[2], b0, b1); unpack2(Sf[3], b2, b3);
            *(float4*)oSf       = make_float4(a0, a1, a2, a3);
            *(float4*)(oSf + 4) = make_float4(b0, b1, b2, b3);

            #pragma unroll
            for (int p = 0; p < 4; p++) {
                float* oSs = out + (size_t)BH*KF*VF + (size_t)bh*KS*VS + (size_t)(4*l + p)*VS + 8*w;
                float c0,c1,c2,c3,d0,d1,d2,d3;
                unpack2(Ss[p][0], c0, c1); unpack2(Ss[p][1], c2, c3);
                unpack2(Ss[p][2], d0, d1); unpack2(Ss[p][3], d2, d3);
                *(float4*)oSs       = make_float4(c0, c1, c2, c3);
                *(float4*)(oSs + 4) = make_float4(d0, d1, d2, d3);
            }
        }
    }
}

extern "C" void kernel_launch(void* const* d_in, const int* in_sizes, int n_in,
                              void* d_out, int out_size) {
    (void)in_sizes; (void)n_in; (void)out_size;
    e90_kernel<<<BH, 288>>>(
        (const float*)d_in[0],  (const float*)d_in[1],  (const float*)d_in[2],
        (const float*)d_in[3],  (const float*)d_in[4],  (const float*)d_in[5],
        (const float*)d_in[6],  (const float*)d_in[7],  (const float*)d_in[8],
        (const float*)d_in[9],  (const float*)d_in[10], (const float*)d_in[11],
        (const float*)d_in[12], (float*)d_out);
}

// round 16
// speedup vs baseline: 1.6704x; 1.0587x over previous
#include <cuda_runtime.h>

typedef unsigned long long u64;
typedef unsigned int u32;

#define T_STEPS 2048
#define NB 8
#define NH 16
#define BH (NB*NH)
#define KF 32
#define VF 64
#define KS 128
#define VS 64

// ---- packed f32x2 helpers ----
__device__ __forceinline__ u64 pack2(float lo, float hi) {
    u64 r;
    asm("mov.b64 %0, {%1, %2};" : "=l"(r) : "r"(__float_as_uint(lo)), "r"(__float_as_uint(hi)));
    return r;
}
__device__ __forceinline__ void unpack2(u64 a, float& lo, float& hi) {
    u32 l, h;
    asm("mov.b64 {%0, %1}, %2;" : "=r"(l), "=r"(h) : "l"(a));
    lo = __uint_as_float(l); hi = __uint_as_float(h);
}
__device__ __forceinline__ u64 fma2_(u64 a, u64 b, u64 c) {
    u64 d; asm("fma.rn.f32x2 %0, %1, %2, %3;" : "=l"(d) : "l"(a), "l"(b), "l"(c)); return d;
}
__device__ __forceinline__ u64 mul2_(u64 a, u64 b) {
    u64 d; asm("mul.rn.f32x2 %0, %1, %2;" : "=l"(d) : "l"(a), "l"(b)); return d;
}
__device__ __forceinline__ u64 add2_(u64 a, u64 b) {
    u64 d; asm("add.rn.f32x2 %0, %1, %2;" : "=l"(d) : "l"(a), "l"(b)); return d;
}
__device__ __forceinline__ u64 shfl_xor_u64(u64 v, int m) {
    u32 lo, hi;
    asm("mov.b64 {%0, %1}, %2;" : "=r"(lo), "=r"(hi) : "l"(v));
    lo = __shfl_xor_sync(0xffffffffu, lo, m);
    hi = __shfl_xor_sync(0xffffffffu, hi, m);
    u64 r;
    asm("mov.b64 %0, {%1, %2};" : "=l"(r) : "r"(lo), "r"(hi));
    return r;
}

// ---- mbarrier helpers ----
__device__ __forceinline__ void mbar_init(u32 addr, u32 count) {
    asm volatile("mbarrier.init.shared.b64 [%0], %1;" :: "r"(addr), "r"(count) : "memory");
}
__device__ __forceinline__ void mbar_arrive(u32 addr) {
    asm volatile("mbarrier.arrive.release.cta.shared::cta.b64 _, [%0];" :: "r"(addr) : "memory");
}
__device__ __forceinline__ void mbar_wait(u32 addr, u32 parity) {
    asm volatile(
        "{\n\t.reg .pred P;\n\t"
        "WL%=:\n\t"
        "mbarrier.try_wait.parity.acquire.cta.shared::cta.b64 P, [%0], %1, 0x989680;\n\t"
        "@P bra WD%=;\n\t"
        "bra WL%=;\n\t"
        "WD%=:\n\t}"
        :: "r"(addr), "r"(parity) : "memory");
}
__device__ __forceinline__ void cp16(u32 dst, const void* s) {
    asm volatile("cp.async.cg.shared.global [%0], [%1], 16;" :: "r"(dst), "l"(s));
}
__device__ __forceinline__ void cp4(u32 dst, const void* s) {
    asm volatile("cp.async.ca.shared.global [%0], [%1], 4;" :: "r"(dst), "l"(s));
}

// smem per-step stage (floats) — natural order, no swizzle:
// [0,32) kf | [32,64) qf | [64,192) ks | [192,320) qs
// [320,384) vf | [384,448) vs | [448,453) scalars {df,ds,g,mf,ms} | pad 456
#define STEP_F 456
#define MEGA   8                 // steps per mega-stage (even; also decay-rescale period)
#define NMEGA  3                 // ring = 24 steps = 43.8 KB static smem
#define NMEGAI (T_STEPS/MEGA)    // 256 mega-iterations

// per-step register staging (double-buffered software pipeline)
struct SR {
    float4 sc4;            // df, ds, g, mf
    float  msv;            // ms
    float  kf, qf;         // fast k/q, row = lane
    float4 ks4, qs4;       // slow k/q, rows 4l..4l+3
    ulonglong2 vfA, vfB;   // v_fast cols 8w..8w+7 packed in pairs
    ulonglong2 vsA, vsB;   // v_slow cols 8w..8w+7
};

__device__ __forceinline__ void loadregs(SR& r, const float* cur, int l, int w) {
    r.sc4 = *(const float4*)(cur + 448);
    r.msv = cur[452];
    r.kf  = cur[l];
    r.qf  = cur[32 + l];
    r.ks4 = *(const float4*)(cur + 64  + 4*l);
    r.qs4 = *(const float4*)(cur + 192 + 4*l);
    r.vfA = *(const ulonglong2*)(cur + 320 + 8*w);
    r.vfB = *(const ulonglong2*)(cur + 320 + 8*w + 4);
    r.vsA = *(const ulonglong2*)(cur + 384 + 8*w);
    r.vsB = *(const ulonglong2*)(cur + 384 + 8*w + 4);
}

__global__ __launch_bounds__(288, 1)
void e90_kernel(const float* __restrict__ k_fast, const float* __restrict__ v_fast,
                const float* __restrict__ q_fast, const float* __restrict__ decay_fast,
                const float* __restrict__ k_slow, const float* __restrict__ v_slow,
                const float* __restrict__ q_slow, const float* __restrict__ decay_slow,
                const float* __restrict__ slow_gate, const float* __restrict__ mix_fast,
                const float* __restrict__ mix_slow, const float* __restrict__ S_fast0,
                const float* __restrict__ S_slow0, float* __restrict__ out)
{
    __shared__ __align__(16) float ring[NMEGA * MEGA * STEP_F];
    __shared__ __align__(8)  u64  mbar[2 * NMEGA];   // [0..2] full, [3..5] empty

    const int tid = threadIdx.x;
    const int bh  = blockIdx.x;

    const u32 sb = (u32)__cvta_generic_to_shared(ring);
    const u32 bb = (u32)__cvta_generic_to_shared(mbar);

    if (tid == 0) {
        #pragma unroll
        for (int i = 0; i < NMEGA; i++) {
            mbar_init(bb + i*8, 32);                 // full: 32 producer-lane arrives
            mbar_init(bb + (NMEGA + i)*8, 8);        // empty: 8 consumer-warp arrives
        }
    }
    __syncthreads();   // the ONLY block barrier

    if (tid >= 256) {
        // ================= PRODUCER WARP =================
        const int lane = tid - 256;
        const float* src[4];
        int off[4], strd[4], wid[4];
        #pragma unroll
        for (int r = 0; r < 4; r++) {
            int c = r*32 + lane;
            src[r] = 0; off[r] = -1; strd[r] = 0; wid[r] = 1;
            if (c < 8)        {               src[r] = k_fast + (size_t)bh*KF + c*4;  off[r] = c*4;           strd[r] = BH*KF; }
            else if (c < 16)  { int g = c-8;  src[r] = q_fast + (size_t)bh*KF + g*4;  off[r] = 32  + g*4;     strd[r] = BH*KF; }
            else if (c < 48)  { int g = c-16; src[r] = k_slow + (size_t)bh*KS + g*4;  off[r] = 64  + g*4;     strd[r] = BH*KS; }
            else if (c < 80)  { int g = c-48; src[r] = q_slow + (size_t)bh*KS + g*4;  off[r] = 192 + g*4;     strd[r] = BH*KS; }
            else if (c < 96)  { int g = c-80; src[r] = v_fast + (size_t)bh*VF + g*4;  off[r] = 320 + g*4;     strd[r] = BH*VF; }
            else if (c < 112) { int g = c-96; src[r] = v_slow + (size_t)bh*VS + g*4;  off[r] = 384 + g*4;     strd[r] = BH*VS; }
            else if (c < 117) {
                const float* a5[5] = {decay_fast, decay_slow, slow_gate, mix_fast, mix_slow};
                src[r] = a5[c-112] + bh; off[r] = 448 + (c-112); strd[r] = BH; wid[r] = 0;
            }
        }

        int sm = 0; u32 eph = 1;   // fresh empty barriers pass parity-1 wait immediately
        for (int m = 0; m < NMEGAI; m++) {
            mbar_wait(bb + (NMEGA + sm)*8, eph);     // wait stage free
            u32 stg = sb + (u32)(sm * MEGA * STEP_F) * 4u;
            #pragma unroll
            for (int s = 0; s < MEGA; s++) {
                u32 stp = stg + (u32)(s * STEP_F) * 4u;
                #pragma unroll
                for (int r = 0; r < 4; r++) {
                    if (off[r] >= 0) {
                        u32 dst = stp + (u32)off[r] * 4u;
                        if (wid[r]) cp16(dst, src[r]); else cp4(dst, src[r]);
                        src[r] += strd[r];
                    }
                }
            }
            asm volatile("cp.async.mbarrier.arrive.noinc.shared.b64 [%0];" :: "r"(bb + sm*8) : "memory");
            if (sm == NMEGA-1) { sm = 0; eph ^= 1; } else sm++;
        }
    } else {
        // ================= 8 CONSUMER WARPS =================
        // warp w owns output columns 8w..8w+7; lane l owns fast row l + slow rows 4l..4l+3
        const int w = tid >> 5;
        const int l = tid & 31;

        // states packed along COLUMNS.
        // Slow state is kept in DECAY-FACTORED form within each mega-stage:
        //   Ss_reg = S_true / De_run  (De_run = prod of effective slow decays this stage)
        // and re-trued by Ss *= De_run at each stage end.
        u64 Sf[4], Ss[4][4];
        {
            const float* p0 = S_fast0 + (size_t)bh*KF*VF + (size_t)l*VF + 8*w;
            float4 a = *(const float4*)p0;
            float4 b = *(const float4*)(p0 + 4);
            Sf[0] = pack2(a.x, a.y); Sf[1] = pack2(a.z, a.w);
            Sf[2] = pack2(b.x, b.y); Sf[3] = pack2(b.z, b.w);
            #pragma unroll
            for (int p = 0; p < 4; p++) {
                const float* p1 = S_slow0 + (size_t)bh*KS*VS + (size_t)(4*l + p)*VS + 8*w;
                float4 c = *(const float4*)p1;
                float4 d = *(const float4*)(p1 + 4);
                Ss[p][0] = pack2(c.x, c.y); Ss[p][1] = pack2(c.z, c.w);
                Ss[p][2] = pack2(d.x, d.y); Ss[p][3] = pack2(d.z, d.w);
            }
        }

        float* outO = out + (size_t)BH*(KF*VF + KS*VS) + (size_t)bh*VF + 8*w;
        const bool elect   = (l == 0);
        const bool writer  = ((l & 3) == 0);     // lanes 0,4,..,28 each write one column
        const int  wcol    = l >> 2;             // column (within the warp's 8) this lane writes
        const bool hi16    = (l & 16) != 0;
        const bool hi8     = (l & 8)  != 0;
        const bool hi4     = (l & 4)  != 0;

        float De_run = 1.0f;   // running slow-decay product within the current mega-stage

        // state math for one step; emits the step's mixed col-pair partials a0..a3
        auto compute_state = [&](const SR& r, u64& a0, u64& a1, u64& a2, u64& a3) {
            float df = r.sc4.x, ds = r.sc4.y, g = r.sc4.z, mf = r.sc4.w;
            float ms = r.msv;
            float de = 1.0f + g * (ds - 1.0f);   // effective slow decay: g*ds + (1-g)

            De_run *= de;
            float gd = __fdividef(g, De_run);    // fold gate AND 1/De into the vs prep
            float msD = ms * De_run;             // un-factor at readout

            u64 df2 = pack2(df, df);
            u64 gd2 = pack2(gd, gd);

            // fast state (unfactored — the mul IS the k*v product, no savings possible)
            u64 vf2[4] = { r.vfA.x, r.vfA.y, r.vfB.x, r.vfB.y };
            u64 kf2 = pack2(r.kf, r.kf);
            u64 qf2 = pack2(r.qf, r.qf);
            u64 accf[4];
            #pragma unroll
            for (int j = 0; j < 4; j++) {
                Sf[j]   = fma2_(df2, Sf[j], mul2_(kf2, vf2[j]));
                accf[j] = mul2_(qf2, Sf[j]);
            }

            // slow state, factored: T += k (x) (g/De * v)  — ONE fma per element-pair
            u64 vs2[4] = { mul2_(gd2, r.vsA.x), mul2_(gd2, r.vsA.y),
                           mul2_(gd2, r.vsB.x), mul2_(gd2, r.vsB.y) };
            const float ksv[4] = { r.ks4.x, r.ks4.y, r.ks4.z, r.ks4.w };
            const float qsv[4] = { r.qs4.x, r.qs4.y, r.qs4.z, r.qs4.w };
            u64 accs[4];
            {
                u64 k2 = pack2(ksv[0], ksv[0]);
                u64 q2 = pack2(qsv[0], qsv[0]);
                #pragma unroll
                for (int j = 0; j < 4; j++) {
                    Ss[0][j] = fma2_(k2, vs2[j], Ss[0][j]);
                    accs[j]  = mul2_(q2, Ss[0][j]);
                }
            }
            #pragma unroll
            for (int p = 1; p < 4; p++) {
                u64 k2 = pack2(ksv[p], ksv[p]);
                u64 q2 = pack2(qsv[p], qsv[p]);
                #pragma unroll
                for (int j = 0; j < 4; j++) {
                    Ss[p][j] = fma2_(k2, vs2[j], Ss[p][j]);
                    accs[j]  = fma2_(q2, Ss[p][j], accs[j]);
                }
            }

            // mix: q.S_true = De_run * (q.T) -> fold De_run into ms
            u64 mf2 = pack2(mf, mf), ms2 = pack2(msD, msD);
            a0 = fma2_(ms2, accs[0], mul2_(mf2, accf[0]));  // cols 8w+0,1
            a1 = fma2_(ms2, accs[1], mul2_(mf2, accf[1]));  // cols 8w+2,3
            a2 = fma2_(ms2, accs[2], mul2_(mf2, accf[2]));  // cols 8w+4,5
            a3 = fma2_(ms2, accs[3], mul2_(mf2, accf[3]));  // cols 8w+6,7
        };

        // stash for the even step of each pair
        u64 X0 = 0, X1 = 0, X2 = 0, X3 = 0;
        float* dstX = 0;

        SR R[2];
        int sm = 0; u32 cph = 0;
        mbar_wait(bb + 0, 0);
        loadregs(R[0], ring, l, w);

        for (int m = 0; m < NMEGAI; m++) {
            const float* base = ring + sm * MEGA * STEP_F;
            const int nsm = (sm == NMEGA-1) ? 0 : sm+1;
            const u32 nc  = (sm == NMEGA-1) ? (cph ^ 1) : cph;
            #pragma unroll
            for (int s = 0; s < MEGA; s++) {
                if (s < MEGA-1) {
                    loadregs(R[(s+1)&1], base + (s+1)*STEP_F, l, w);
                } else if (m < NMEGAI-1) {
                    // cross-boundary preload hidden under this final compute
                    mbar_wait(bb + nsm*8, nc);
                    loadregs(R[0], ring + nsm * MEGA * STEP_F, l, w);
                }

                u64 a0, a1, a2, a3;
                compute_state(R[s&1], a0, a1, a2, a3);

                if ((s & 1) == 0) {
                    // even step: stash partials, defer reduction
                    X0 = a0; X1 = a1; X2 = a2; X3 = a3;
                    dstX = outO;
                } else {
                    // odd step: ONE batched value-halving butterfly for both steps
                    u64 kx0 = hi16 ? X2 : X0, sx0 = hi16 ? X0 : X2;
                    u64 kx1 = hi16 ? X3 : X1, sx1 = hi16 ? X1 : X3;
                    u64 ky0 = hi16 ? a2 : a0, sy0 = hi16 ? a0 : a2;
                    u64 ky1 = hi16 ? a3 : a1, sy1 = hi16 ? a1 : a3;
                    kx0 = add2_(kx0, shfl_xor_u64(sx0, 16));
                    kx1 = add2_(kx1, shfl_xor_u64(sx1, 16));
                    ky0 = add2_(ky0, shfl_xor_u64(sy0, 16));
                    ky1 = add2_(ky1, shfl_xor_u64(sy1, 16));
                    u64 kx = hi8 ? kx1 : kx0, sx = hi8 ? kx0 : kx1;
                    u64 ky = hi8 ? ky1 : ky0, sy = hi8 ? ky0 : ky1;
                    kx = add2_(kx, shfl_xor_u64(sx, 8));
                    ky = add2_(ky, shfl_xor_u64(sy, 8));
                    float xa, xb, ya, yb;
                    unpack2(kx, xa, xb);
                    unpack2(ky, ya, yb);
                    u64 Zk = hi4 ? pack2(xb, yb) : pack2(xa, ya);
                    u64 Zs = hi4 ? pack2(xa, ya) : pack2(xb, yb);
                    u64 Z  = add2_(Zk, shfl_xor_u64(Zs, 4));
                    Z = add2_(Z, shfl_xor_u64(Z, 2));
                    Z = add2_(Z, shfl_xor_u64(Z, 1));
                    if (writer) {
                        float xv, yv;
                        unpack2(Z, xv, yv);
                        dstX[wcol] = xv;   // even step's output
                        outO[wcol] = yv;   // odd step's output
                    }
                }
                outO += (size_t)BH * VF;
            }

            // re-true the factored slow state at the stage boundary
            {
                u64 D2 = pack2(De_run, De_run);
                #pragma unroll
                for (int p = 0; p < 4; p++)
                    #pragma unroll
                    for (int j = 0; j < 4; j++)
                        Ss[p][j] = mul2_(D2, Ss[p][j]);
                De_run = 1.0f;
            }

            if (elect) mbar_arrive(bb + (NMEGA + sm)*8);   // stage consumed (all reads done)
            sm = nsm; cph = nc;
        }

        // final states (Ss re-trued by the last stage's rescale)
        {
            float* oSf = out + (size_t)bh*KF*VF + (size_t)l*VF + 8*w;
            float a0,a1,a2,a3,b0,b1,b2,b3;
            unpack2(Sf[0], a0, a1); unpack2(Sf[1], a2, a3);
            unpack2(Sf[2], b0, b1); unpack2(Sf[3], b2, b3);
            *(float4*)oSf       = make_float4(a0, a1, a2, a3);
            *(float4*)(oSf + 4) = make_float4(b0, b1, b2, b3);

            #pragma unroll
            for (int p = 0; p < 4; p++) {
                float* oSs = out + (size_t)BH*KF*VF + (size_t)bh*KS*VS + (size_t)(4*l + p)*VS + 8*w;
                float c0,c1,c2,c3,d0,d1,d2,d3;
                unpack2(Ss[p][0], c0, c1); unpack2(Ss[p][1], c2, c3);
                unpack2(Ss[p][2], d0, d1); unpack2(Ss[p][3], d2, d3);
                *(float4*)oSs       = make_float4(c0, c1, c2, c3);
                *(float4*)(oSs + 4) = make_float4(d0, d1, d2, d3);
            }
        }
    }
}

extern "C" void kernel_launch(void* const* d_in, const int* in_sizes, int n_in,
                              void* d_out, int out_size) {
    (void)in_sizes; (void)n_in; (void)out_size;
    e90_kernel<<<BH, 288>>>(
        (const float*)d_in[0],  (const float*)d_in[1],  (const float*)d_in[2],
        (const float*)d_in[3],  (const float*)d_in[4],  (const float*)d_in[5],
        (const float*)d_in[6],  (const float*)d_in[7],  (const float*)d_in[8],
        (const float*)d_in[9],  (const float*)d_in[10], (const float*)d_in[11],
        (const float*)d_in[12], (float*)d_out);
}

// round 17
// speedup vs baseline: 1.6812x; 1.0065x over previous
#include <cuda_runtime.h>

typedef unsigned long long u64;
typedef unsigned int u32;

#define T_STEPS 2048
#define NB 8
#define NH 16
#define BH (NB*NH)
#define KF 32
#define VF 64
#define KS 128
#define VS 64

// ---- packed f32x2 helpers ----
__device__ __forceinline__ u64 pack2(float lo, float hi) {
    u64 r;
    asm("mov.b64 %0, {%1, %2};" : "=l"(r) : "r"(__float_as_uint(lo)), "r"(__float_as_uint(hi)));
    return r;
}
__device__ __forceinline__ void unpack2(u64 a, float& lo, float& hi) {
    u32 l, h;
    asm("mov.b64 {%0, %1}, %2;" : "=r"(l), "=r"(h) : "l"(a));
    lo = __uint_as_float(l); hi = __uint_as_float(h);
}
__device__ __forceinline__ u64 fma2_(u64 a, u64 b, u64 c) {
    u64 d; asm("fma.rn.f32x2 %0, %1, %2, %3;" : "=l"(d) : "l"(a), "l"(b), "l"(c)); return d;
}
__device__ __forceinline__ u64 mul2_(u64 a, u64 b) {
    u64 d; asm("mul.rn.f32x2 %0, %1, %2;" : "=l"(d) : "l"(a), "l"(b)); return d;
}
__device__ __forceinline__ u64 add2_(u64 a, u64 b) {
    u64 d; asm("add.rn.f32x2 %0, %1, %2;" : "=l"(d) : "l"(a), "l"(b)); return d;
}
__device__ __forceinline__ u64 shfl_xor_u64(u64 v, int m) {
    u32 lo, hi;
    asm("mov.b64 {%0, %1}, %2;" : "=r"(lo), "=r"(hi) : "l"(v));
    lo = __shfl_xor_sync(0xffffffffu, lo, m);
    hi = __shfl_xor_sync(0xffffffffu, hi, m);
    u64 r;
    asm("mov.b64 %0, {%1, %2};" : "=l"(r) : "r"(lo), "r"(hi));
    return r;
}

// ---- mbarrier helpers ----
__device__ __forceinline__ void mbar_init(u32 addr, u32 count) {
    asm volatile("mbarrier.init.shared.b64 [%0], %1;" :: "r"(addr), "r"(count) : "memory");
}
__device__ __forceinline__ void mbar_arrive(u32 addr) {
    asm volatile("mbarrier.arrive.release.cta.shared::cta.b64 _, [%0];" :: "r"(addr) : "memory");
}
__device__ __forceinline__ void mbar_wait(u32 addr, u32 parity) {
    asm volatile(
        "{\n\t.reg .pred P;\n\t"
        "WL%=:\n\t"
        "mbarrier.try_wait.parity.acquire.cta.shared::cta.b64 P, [%0], %1, 0x989680;\n\t"
        "@P bra WD%=;\n\t"
        "bra WL%=;\n\t"
        "WD%=:\n\t}"
        :: "r"(addr), "r"(parity) : "memory");
}
__device__ __forceinline__ void cp16(u32 dst, const void* s) {
    asm volatile("cp.async.cg.shared.global [%0], [%1], 16;" :: "r"(dst), "l"(s));
}
__device__ __forceinline__ void cp4(u32 dst, const void* s) {
    asm volatile("cp.async.ca.shared.global [%0], [%1], 4;" :: "r"(dst), "l"(s));
}

// smem per-step stage (floats) — natural order, no swizzle:
// [0,32) kf | [32,64) qf | [64,192) ks | [192,320) qs
// [320,384) vf | [384,448) vs | [448,453) scalars {df,ds,g,mf,ms} | pad 456
#define STEP_F 456
#define MEGA   8                 // steps per mega-stage (even; also decay-rescale period)
#define NMEGA  3                 // ring = 24 steps = 43.8 KB static smem
#define NMEGAI (T_STEPS/MEGA)    // 256 mega-iterations

// per-step register staging (double-buffered software pipeline)
struct SR {
    float4 sc4;            // df, ds, g, mf
    float  msv;            // ms
    float  kf, qf;         // fast k/q, row = lane
    float4 ks4, qs4;       // slow k/q, rows 4l..4l+3
    ulonglong2 vfA, vfB;   // v_fast cols 8w..8w+7 packed in pairs
    ulonglong2 vsA, vsB;   // v_slow cols 8w..8w+7
};

__device__ __forceinline__ void loadregs(SR& r, const float* cur, int l, int w) {
    r.sc4 = *(const float4*)(cur + 448);
    r.msv = cur[452];
    r.kf  = cur[l];
    r.qf  = cur[32 + l];
    r.ks4 = *(const float4*)(cur + 64  + 4*l);
    r.qs4 = *(const float4*)(cur + 192 + 4*l);
    r.vfA = *(const ulonglong2*)(cur + 320 + 8*w);
    r.vfB = *(const ulonglong2*)(cur + 320 + 8*w + 4);
    r.vsA = *(const ulonglong2*)(cur + 384 + 8*w);
    r.vsB = *(const ulonglong2*)(cur + 384 + 8*w + 4);
}

__global__ __launch_bounds__(288, 1)
void e90_kernel(const float* __restrict__ k_fast, const float* __restrict__ v_fast,
                const float* __restrict__ q_fast, const float* __restrict__ decay_fast,
                const float* __restrict__ k_slow, const float* __restrict__ v_slow,
                const float* __restrict__ q_slow, const float* __restrict__ decay_slow,
                const float* __restrict__ slow_gate, const float* __restrict__ mix_fast,
                const float* __restrict__ mix_slow, const float* __restrict__ S_fast0,
                const float* __restrict__ S_slow0, float* __restrict__ out)
{
    __shared__ __align__(16) float ring[NMEGA * MEGA * STEP_F];
    __shared__ __align__(8)  u64  mbar[2 * NMEGA];   // [0..2] full, [3..5] empty

    const int tid = threadIdx.x;
    const int bh  = blockIdx.x;

    const u32 sb = (u32)__cvta_generic_to_shared(ring);
    const u32 bb = (u32)__cvta_generic_to_shared(mbar);

    if (tid == 0) {
        #pragma unroll
        for (int i = 0; i < NMEGA; i++) {
            mbar_init(bb + i*8, 32);                 // full: 32 producer-lane arrives
            mbar_init(bb + (NMEGA + i)*8, 8);        // empty: 8 consumer-warp arrives
        }
    }
    __syncthreads();   // the ONLY block barrier

    if (tid >= 256) {
        // ================= PRODUCER WARP =================
        const int lane = tid - 256;
        const float* src[4];
        int off[4], strd[4], wid[4];
        #pragma unroll
        for (int r = 0; r < 4; r++) {
            int c = r*32 + lane;
            src[r] = 0; off[r] = -1; strd[r] = 0; wid[r] = 1;
            if (c < 8)        {               src[r] = k_fast + (size_t)bh*KF + c*4;  off[r] = c*4;           strd[r] = BH*KF; }
            else if (c < 16)  { int g = c-8;  src[r] = q_fast + (size_t)bh*KF + g*4;  off[r] = 32  + g*4;     strd[r] = BH*KF; }
            else if (c < 48)  { int g = c-16; src[r] = k_slow + (size_t)bh*KS + g*4;  off[r] = 64  + g*4;     strd[r] = BH*KS; }
            else if (c < 80)  { int g = c-48; src[r] = q_slow + (size_t)bh*KS + g*4;  off[r] = 192 + g*4;     strd[r] = BH*KS; }
            else if (c < 96)  { int g = c-80; src[r] = v_fast + (size_t)bh*VF + g*4;  off[r] = 320 + g*4;     strd[r] = BH*VF; }
            else if (c < 112) { int g = c-96; src[r] = v_slow + (size_t)bh*VS + g*4;  off[r] = 384 + g*4;     strd[r] = BH*VS; }
            else if (c < 117) {
                const float* a5[5] = {decay_fast, decay_slow, slow_gate, mix_fast, mix_slow};
                src[r] = a5[c-112] + bh; off[r] = 448 + (c-112); strd[r] = BH; wid[r] = 0;
            }
        }

        int sm = 0; u32 eph = 1;   // fresh empty barriers pass parity-1 wait immediately
        for (int m = 0; m < NMEGAI; m++) {
            mbar_wait(bb + (NMEGA + sm)*8, eph);     // wait stage free
            u32 stg = sb + (u32)(sm * MEGA * STEP_F) * 4u;
            #pragma unroll
            for (int s = 0; s < MEGA; s++) {
                u32 stp = stg + (u32)(s * STEP_F) * 4u;
                #pragma unroll
                for (int r = 0; r < 4; r++) {
                    if (off[r] >= 0) {
                        u32 dst = stp + (u32)off[r] * 4u;
                        if (wid[r]) cp16(dst, src[r]); else cp4(dst, src[r]);
                        src[r] += strd[r];
                    }
                }
            }
            asm volatile("cp.async.mbarrier.arrive.noinc.shared.b64 [%0];" :: "r"(bb + sm*8) : "memory");
            if (sm == NMEGA-1) { sm = 0; eph ^= 1; } else sm++;
        }
    } else {
        // ================= 8 CONSUMER WARPS =================
        // warp w owns output columns 8w..8w+7; lane l owns fast row l + slow rows 4l..4l+3
        const int w = tid >> 5;
        const int l = tid & 31;

        // states packed along COLUMNS.
        // BOTH states kept DECAY-FACTORED within each mega-stage:
        //   Sf_reg = Sf_true / Df_run ; Ss_reg = Ss_true / De_run
        // re-trued by *= run at each stage end.
        u64 Sf[4], Ss[4][4];
        {
            const float* p0 = S_fast0 + (size_t)bh*KF*VF + (size_t)l*VF + 8*w;
            float4 a = *(const float4*)p0;
            float4 b = *(const float4*)(p0 + 4);
            Sf[0] = pack2(a.x, a.y); Sf[1] = pack2(a.z, a.w);
            Sf[2] = pack2(b.x, b.y); Sf[3] = pack2(b.z, b.w);
            #pragma unroll
            for (int p = 0; p < 4; p++) {
                const float* p1 = S_slow0 + (size_t)bh*KS*VS + (size_t)(4*l + p)*VS + 8*w;
                float4 c = *(const float4*)p1;
                float4 d = *(const float4*)(p1 + 4);
                Ss[p][0] = pack2(c.x, c.y); Ss[p][1] = pack2(c.z, c.w);
                Ss[p][2] = pack2(d.x, d.y); Ss[p][3] = pack2(d.z, d.w);
            }
        }

        float* outO = out + (size_t)BH*(KF*VF + KS*VS) + (size_t)bh*VF + 8*w;
        const bool elect   = (l == 0);
        const bool writer  = ((l & 3) == 0);     // lanes 0,4,..,28 each write one column
        const int  wcol    = l >> 2;             // column (within the warp's 8) this lane writes
        const bool hi16    = (l & 16) != 0;
        const bool hi8     = (l & 8)  != 0;
        const bool hi4     = (l & 4)  != 0;

        float De_run = 1.0f;   // running slow-decay product (current mega-stage)
        float Df_run = 1.0f;   // running fast-decay product (current mega-stage)

        // state math for one step; emits the step's mixed col-pair partials a0..a3
        auto compute_state = [&](const SR& r, u64& a0, u64& a1, u64& a2, u64& a3) {
            float df = r.sc4.x, ds = r.sc4.y, g = r.sc4.z, mf = r.sc4.w;
            float ms = r.msv;
            float de = 1.0f + g * (ds - 1.0f);   // effective slow decay: g*ds + (1-g)

            De_run *= de;
            Df_run *= df;
            float gd  = __fdividef(g, De_run);   // gate AND 1/De folded into vs prep
            float kfd = __fdividef(r.kf, Df_run);// fast k scaled by 1/Df
            float msD = ms * De_run;             // un-factor slow at readout
            float qfd = r.qf * (mf * Df_run);    // un-factor fast + fold mf at readout

            u64 gd2  = pack2(gd, gd);
            u64 kfd2 = pack2(kfd, kfd);
            u64 qfd2 = pack2(qfd, qfd);

            // fast state, factored: Tf += (kf/Df) (x) vf  — ONE fma per element-pair
            u64 vf2[4] = { r.vfA.x, r.vfA.y, r.vfB.x, r.vfB.y };
            u64 accf[4];
            #pragma unroll
            for (int j = 0; j < 4; j++) {
                Sf[j]   = fma2_(kfd2, vf2[j], Sf[j]);
                accf[j] = mul2_(qfd2, Sf[j]);        // pre-mixed: includes mf*Df_run
            }

            // slow state, factored: T += k (x) (g/De * v)  — ONE fma per element-pair
            u64 vs2[4] = { mul2_(gd2, r.vsA.x), mul2_(gd2, r.vsA.y),
                           mul2_(gd2, r.vsB.x), mul2_(gd2, r.vsB.y) };
            const float ksv[4] = { r.ks4.x, r.ks4.y, r.ks4.z, r.ks4.w };
            const float qsv[4] = { r.qs4.x, r.qs4.y, r.qs4.z, r.qs4.w };
            u64 accs[4];
            {
                u64 k2 = pack2(ksv[0], ksv[0]);
                u64 q2 = pack2(qsv[0], qsv[0]);
                #pragma unroll
                for (int j = 0; j < 4; j++) {
                    Ss[0][j] = fma2_(k2, vs2[j], Ss[0][j]);
                    accs[j]  = mul2_(q2, Ss[0][j]);
                }
            }
            #pragma unroll
            for (int p = 1; p < 4; p++) {
                u64 k2 = pack2(ksv[p], ksv[p]);
                u64 q2 = pack2(qsv[p], qsv[p]);
                #pragma unroll
                for (int j = 0; j < 4; j++) {
                    Ss[p][j] = fma2_(k2, vs2[j], Ss[p][j]);
                    accs[j]  = fma2_(q2, Ss[p][j], accs[j]);
                }
            }

            // mix: accf is pre-scaled by mf*Df; fold ms*De into accs here
            u64 ms2 = pack2(msD, msD);
            a0 = fma2_(ms2, accs[0], accf[0]);  // cols 8w+0,1
            a1 = fma2_(ms2, accs[1], accf[1]);  // cols 8w+2,3
            a2 = fma2_(ms2, accs[2], accf[2]);  // cols 8w+4,5
            a3 = fma2_(ms2, accs[3], accf[3]);  // cols 8w+6,7
        };

        // stash for the even step of each pair
        u64 X0 = 0, X1 = 0, X2 = 0, X3 = 0;
        float* dstX = 0;

        SR R[2];
        int sm = 0; u32 cph = 0;
        mbar_wait(bb + 0, 0);
        loadregs(R[0], ring, l, w);

        for (int m = 0; m < NMEGAI; m++) {
            const float* base = ring + sm * MEGA * STEP_F;
            const int nsm = (sm == NMEGA-1) ? 0 : sm+1;
            const u32 nc  = (sm == NMEGA-1) ? (cph ^ 1) : cph;
            #pragma unroll
            for (int s = 0; s < MEGA; s++) {
                if (s < MEGA-1) {
                    loadregs(R[(s+1)&1], base + (s+1)*STEP_F, l, w);
                } else if (m < NMEGAI-1) {
                    // cross-boundary preload hidden under this final compute
                    mbar_wait(bb + nsm*8, nc);
                    loadregs(R[0], ring + nsm * MEGA * STEP_F, l, w);
                }

                u64 a0, a1, a2, a3;
                compute_state(R[s&1], a0, a1, a2, a3);

                if ((s & 1) == 0) {
                    // even step: stash partials, defer reduction
                    X0 = a0; X1 = a1; X2 = a2; X3 = a3;
                    dstX = outO;
                } else {
                    // odd step: ONE batched value-halving butterfly for both steps
                    u64 kx0 = hi16 ? X2 : X0, sx0 = hi16 ? X0 : X2;
                    u64 kx1 = hi16 ? X3 : X1, sx1 = hi16 ? X1 : X3;
                    u64 ky0 = hi16 ? a2 : a0, sy0 = hi16 ? a0 : a2;
                    u64 ky1 = hi16 ? a3 : a1, sy1 = hi16 ? a1 : a3;
                    kx0 = add2_(kx0, shfl_xor_u64(sx0, 16));
                    kx1 = add2_(kx1, shfl_xor_u64(sx1, 16));
                    ky0 = add2_(ky0, shfl_xor_u64(sy0, 16));
                    ky1 = add2_(ky1, shfl_xor_u64(sy1, 16));
                    u64 kx = hi8 ? kx1 : kx0, sx = hi8 ? kx0 : kx1;
                    u64 ky = hi8 ? ky1 : ky0, sy = hi8 ? ky0 : ky1;
                    kx = add2_(kx, shfl_xor_u64(sx, 8));
                    ky = add2_(ky, shfl_xor_u64(sy, 8));
                    float xa, xb, ya, yb;
                    unpack2(kx, xa, xb);
                    unpack2(ky, ya, yb);
                    u64 Zk = hi4 ? pack2(xb, yb) : pack2(xa, ya);
                    u64 Zs = hi4 ? pack2(xa, ya) : pack2(xb, yb);
                    u64 Z  = add2_(Zk, shfl_xor_u64(Zs, 4));
                    Z = add2_(Z, shfl_xor_u64(Z, 2));
                    Z = add2_(Z, shfl_xor_u64(Z, 1));
                    if (writer) {
                        float xv, yv;
                        unpack2(Z, xv, yv);
                        dstX[wcol] = xv;   // even step's output
                        outO[wcol] = yv;   // odd step's output
                    }
                }
                outO += (size_t)BH * VF;
            }

            // re-true both factored states at the stage boundary
            {
                u64 Df2 = pack2(Df_run, Df_run);
                u64 De2 = pack2(De_run, De_run);
                #pragma unroll
                for (int j = 0; j < 4; j++)
                    Sf[j] = mul2_(Df2, Sf[j]);
                #pragma unroll
                for (int p = 0; p < 4; p++)
                    #pragma unroll
                    for (int j = 0; j < 4; j++)
                        Ss[p][j] = mul2_(De2, Ss[p][j]);
                Df_run = 1.0f;
                De_run = 1.0f;
            }

            if (elect) mbar_arrive(bb + (NMEGA + sm)*8);   // stage consumed (all reads done)
            sm = nsm; cph = nc;
        }

        // final states (both re-trued by the last stage's rescale)
        {
            float* oSf = out + (size_t)bh*KF*VF + (size_t)l*VF + 8*w;
            float a0,a1,a2,a3,b0,b1,b2,b3;
            unpack2(Sf[0], a0, a1); unpack2(Sf[1], a2, a3);
            unpack2(Sf[2], b0, b1); unpack2(Sf[3], b2, b3);
            *(float4*)oSf       = make_float4(a0, a1, a2, a3);
            *(float4*)(oSf + 4) = make_float4(b0, b1, b2, b3);

            #pragma unroll
            for (int p = 0; p < 4; p++) {
                float* oSs = out + (size_t)BH*KF*VF + (size_t)bh*KS*VS + (size_t)(4*l + p)*VS + 8*w;
                float c0,c1,c2,c3,d0,d1,d2,d3;
                unpack2(Ss[p][0], c0, c1); unpack2(Ss[p][1], c2, c3);
                unpack2(Ss[p][2], d0, d1); unpack2(Ss[p][3], d2, d3);
                *(float4*)oSs       = make_float4(c0, c1, c2, c3);
                *(float4*)(oSs + 4) = make_float4(d0, d1, d2, d3);
            }
        }
    }
}

extern "C" void kernel_launch(void* const* d_in, const int* in_sizes, int n_in,
                              void* d_out, int out_size) {
    (void)in_sizes; (void)n_in; (void)out_size;
    e90_kernel<<<BH, 288>>>(
        (const float*)d_in[0],  (const float*)d_in[1],  (const float*)d_in[2],
        (const float*)d_in[3],  (const float*)d_in[4],  (const float*)d_in[5],
        (const float*)d_in[6],  (const float*)d_in[7],  (const float*)d_in[8],
        (const float*)d_in[9],  (const float*)d_in[10], (const float*)d_in[11],
        (const float*)d_in[12], (float*)d_out);
}